// round 14
// baseline (speedup 1.0000x reference)
#include <cuda_runtime.h>
#include <cuda_bf16.h>
#include <cstdint>

// ---------------------------------------------------------------------------
// Transcoder: pre = (x - bias) @ enc_w^T + enc_b ; top-k ; sparse decode ; MSE
// Round 12: hgemm CTA 128x64, warp tile 32x32, THREE CTAs/SM; cand kernel
// with warp-aggregated histograms. Tail/selection math unchanged (bit-exact).
// ---------------------------------------------------------------------------

#define T_TOK 4096
#define DIN   4096
#define NFEAT 32768
#define DOUTD 4096
#define MAXK  128
#define CAND  96

__device__ float          g_xc[(size_t)T_TOK * DIN];        // centered fp32
__device__ __nv_bfloat16  g_xb[(size_t)T_TOK * DIN];        // centered bf16
__device__ __nv_bfloat16  g_wb[(size_t)NFEAT * DIN];        // enc_w bf16
__device__ __nv_bfloat16  g_approxh[(size_t)T_TOK * NFEAT]; // approx pre (bf16)
__device__ float          g_wT[(size_t)NFEAT * DOUTD];      // dec_w transposed
__device__ int            g_selIdx[(size_t)T_TOK * MAXK];
__device__ float          g_selVal[(size_t)T_TOK * MAXK];
__device__ int            g_dIdx[(size_t)T_TOK * MAXK];
__device__ float          g_dVal[(size_t)T_TOK * MAXK];
__device__ double         g_partial[T_TOK];
__device__ float          g_preFB[(size_t)T_TOK * NFEAT];
__device__ float          g_predFB[(size_t)T_TOK * DOUTD];

#define CPASYNC16(dst, src) \
    asm volatile("cp.async.cg.shared.global [%0], [%1], 16;" \
                 :: "r"(dst), "l"(src) : "memory")

// ---------------------------------------------------------------------------
// 1) center: fp32 + bf16 copies
// ---------------------------------------------------------------------------
__global__ void center_kernel(const float4* __restrict__ x,
                              const float4* __restrict__ bias) {
    size_t n = (size_t)T_TOK * DIN / 4;
    for (size_t i = (size_t)blockIdx.x * blockDim.x + threadIdx.x; i < n;
         i += (size_t)gridDim.x * blockDim.x) {
        float4 a = x[i];
        float4 b = bias[i & (DIN / 4 - 1)];
        float4 r;
        r.x = a.x - b.x; r.y = a.y - b.y; r.z = a.z - b.z; r.w = a.w - b.w;
        ((float4*)g_xc)[i] = r;
        __nv_bfloat162 h0 = __floats2bfloat162_rn(r.x, r.y);
        __nv_bfloat162 h1 = __floats2bfloat162_rn(r.z, r.w);
        uint2 pk;
        pk.x = *(uint32_t*)&h0;
        pk.y = *(uint32_t*)&h1;
        ((uint2*)g_xb)[i] = pk;
    }
}

// ---------------------------------------------------------------------------
// 2) enc_w -> bf16
// ---------------------------------------------------------------------------
__global__ void convertw_kernel(const float4* __restrict__ W) {
    size_t n = (size_t)NFEAT * DIN / 4;
    for (size_t i = (size_t)blockIdx.x * blockDim.x + threadIdx.x; i < n;
         i += (size_t)gridDim.x * blockDim.x) {
        float4 a = W[i];
        __nv_bfloat162 h0 = __floats2bfloat162_rn(a.x, a.y);
        __nv_bfloat162 h1 = __floats2bfloat162_rn(a.z, a.w);
        uint2 pk;
        pk.x = *(uint32_t*)&h0;
        pk.y = *(uint32_t*)&h1;
        ((uint2*)g_wb)[i] = pk;
    }
}

// ---------------------------------------------------------------------------
// 3) transpose dec_w -> g_wT [NFEAT, DOUTD]; 64x64 tile, float4 both ways
// ---------------------------------------------------------------------------
__global__ void __launch_bounds__(256)
transpose_kernel(const float* __restrict__ W) {
    __shared__ float t[64][65];
    int j0 = blockIdx.x * 64;
    int d0 = blockIdx.y * 64;
    int tx = threadIdx.x & 15;
    int ty = threadIdx.x >> 4;
    #pragma unroll
    for (int i = 0; i < 4; i++) {
        int d = ty + i * 16;
        float4 v = *(const float4*)(W + (size_t)(d0 + d) * NFEAT + j0 + tx * 4);
        t[d][tx * 4 + 0] = v.x;
        t[d][tx * 4 + 1] = v.y;
        t[d][tx * 4 + 2] = v.z;
        t[d][tx * 4 + 3] = v.w;
    }
    __syncthreads();
    #pragma unroll
    for (int i = 0; i < 4; i++) {
        int j = ty + i * 16;
        float4 v;
        v.x = t[tx * 4 + 0][j];
        v.y = t[tx * 4 + 1][j];
        v.z = t[tx * 4 + 2][j];
        v.w = t[tx * 4 + 3][j];
        *(float4*)(g_wT + (size_t)(j0 + j) * DOUTD + d0 + tx * 4) = v;
    }
}

// ---------------------------------------------------------------------------
// 4) HMMA approx GEMM: approx[t,f] = bf16(xb[t,:].wb[f,:] + encb[f])
//    CTA 128x64, BK=32, 8 warps (4m x 2n), warp tile 32x32, 2-stage
//    cp.async, THREE CTAs per SM (launch_bounds(256,3), 30KB smem/CTA).
// ---------------------------------------------------------------------------
#define RSTR   80                      // bytes per smem row (32 bf16 + pad)
#define A_SZ   (128 * RSTR)            // 10240 B
#define B_SZ   (64 * RSTR)             // 5120 B
#define STG_SZ (A_SZ + B_SZ)           // 15360 B
#define HG_SMEM (2 * STG_SZ)           // 30720 B
#define NCH    (DIN / 32)              // 128 chunks

__global__ void __launch_bounds__(256, 3)
hgemm_kernel(const float* __restrict__ encb, __nv_bfloat16* __restrict__ C) {
    extern __shared__ char smem[];
    uint32_t sbase;
    asm("{ .reg .u64 t; cvta.to.shared.u64 t, %1; cvt.u32.u64 %0, t; }"
        : "=r"(sbase) : "l"(smem));

    int tid  = threadIdx.x;
    int lane = tid & 31;
    int warp = tid >> 5;
    int wm   = warp & 3;          // 0..3  (32-row quarter)
    int wn   = warp >> 2;         // 0..1  (32-col slice)

    int mBase = blockIdx.x * 128;
    int nBase = blockIdx.y * 64;

    const __nv_bfloat16* gA0 = g_xb + (size_t)mBase * DIN;
    const __nv_bfloat16* gB0 = g_wb + (size_t)nBase * DIN;

    float acc[2][4][4];
    #pragma unroll
    for (int mi = 0; mi < 2; mi++)
        #pragma unroll
        for (int nj = 0; nj < 4; nj++)
            #pragma unroll
            for (int r = 0; r < 4; r++) acc[mi][nj][r] = 0.f;

    int lr = tid >> 2, lq = tid & 3;   // lr 0..63, lq 0..3
    auto load_stage = [&](int kb, int s) {
        uint32_t aB = sbase + s * STG_SZ;
        uint32_t bB = aB + A_SZ;
        #pragma unroll
        for (int i = 0; i < 2; i++) {             // A: 128 rows
            int r = lr + i * 64;
            const __nv_bfloat16* src = gA0 + (size_t)r * DIN + kb + lq * 8;
            CPASYNC16(aB + r * RSTR + lq * 16, src);
        }
        {                                          // B: 64 rows
            const __nv_bfloat16* src = gB0 + (size_t)lr * DIN + kb + lq * 8;
            CPASYNC16(bB + lr * RSTR + lq * 16, src);
        }
        asm volatile("cp.async.commit_group;" ::: "memory");
    };

    load_stage(0, 0);
    asm volatile("cp.async.wait_group 0;" ::: "memory");
    __syncthreads();

    // per-lane ldmatrix components
    int aRow = (lane & 15);
    int aKB  = (lane >> 4) * 16;            // bytes
    int bRow = ((lane >> 4) << 3) + (lane & 7);
    int bKB  = ((lane >> 3) & 1) * 16;      // bytes

    for (int c = 0; c < NCH; c++) {
        int s = c & 1;
        bool has = (c + 1) < NCH;
        if (has) load_stage((c + 1) * 32, s ^ 1);

        uint32_t aB = sbase + s * STG_SZ;
        uint32_t bB = aB + A_SZ;

        #pragma unroll
        for (int ks = 0; ks < 2; ks++) {          // two k16 slices
            uint32_t af[2][4];
            #pragma unroll
            for (int mi = 0; mi < 2; mi++) {
                int row = wm * 32 + mi * 16 + aRow;
                uint32_t sa = aB + row * RSTR + ks * 32 + aKB;
                asm volatile(
                    "ldmatrix.sync.aligned.m8n8.x4.shared.b16 {%0,%1,%2,%3}, [%4];"
                    : "=r"(af[mi][0]), "=r"(af[mi][1]),
                      "=r"(af[mi][2]), "=r"(af[mi][3]) : "r"(sa));
            }
            uint32_t bf[2][4];
            #pragma unroll
            for (int p = 0; p < 2; p++) {
                int row = wn * 32 + p * 16 + bRow;
                uint32_t sb = bB + row * RSTR + ks * 32 + bKB;
                asm volatile(
                    "ldmatrix.sync.aligned.m8n8.x4.shared.b16 {%0,%1,%2,%3}, [%4];"
                    : "=r"(bf[p][0]), "=r"(bf[p][1]),
                      "=r"(bf[p][2]), "=r"(bf[p][3]) : "r"(sb));
            }
            #pragma unroll
            for (int mi = 0; mi < 2; mi++)
                #pragma unroll
                for (int nj = 0; nj < 4; nj++) {
                    uint32_t b0 = bf[nj >> 1][(nj & 1) * 2 + 0];
                    uint32_t b1 = bf[nj >> 1][(nj & 1) * 2 + 1];
                    asm volatile(
                        "mma.sync.aligned.m16n8k16.row.col.f32.bf16.bf16.f32 "
                        "{%0,%1,%2,%3}, {%4,%5,%6,%7}, {%8,%9}, {%0,%1,%2,%3};"
                        : "+f"(acc[mi][nj][0]), "+f"(acc[mi][nj][1]),
                          "+f"(acc[mi][nj][2]), "+f"(acc[mi][nj][3])
                        : "r"(af[mi][0]), "r"(af[mi][1]),
                          "r"(af[mi][2]), "r"(af[mi][3]),
                          "r"(b0), "r"(b1));
                }
        }

        if (has) asm volatile("cp.async.wait_group 0;" ::: "memory");
        __syncthreads();
    }

    // epilogue: add enc_b, convert to bf16, store
    #pragma unroll
    for (int mi = 0; mi < 2; mi++) {
        int m0 = mBase + wm * 32 + mi * 16 + (lane >> 2);
        #pragma unroll
        for (int nj = 0; nj < 4; nj++) {
            int col = nBase + wn * 32 + nj * 8 + (lane & 3) * 2;
            float2 e = *(const float2*)(encb + col);
            __nv_bfloat162 h0 = __floats2bfloat162_rn(acc[mi][nj][0] + e.x,
                                                      acc[mi][nj][1] + e.y);
            __nv_bfloat162 h1 = __floats2bfloat162_rn(acc[mi][nj][2] + e.x,
                                                      acc[mi][nj][3] + e.y);
            *(uint32_t*)(C + (size_t)m0 * NFEAT + col)       = *(uint32_t*)&h0;
            *(uint32_t*)(C + (size_t)(m0 + 8) * NFEAT + col) = *(uint32_t*)&h1;
        }
    }
}

// ---------------------------------------------------------------------------
// 5) candidate select: 2-pass radix top-CAND, warp-aggregated histograms
// ---------------------------------------------------------------------------
__device__ __forceinline__ void hist_add(int* hist, int b) {
    unsigned mask = __match_any_sync(__activemask(), b);
    int leader = __ffs(mask) - 1;
    if ((int)(threadIdx.x & 31) == leader)
        atomicAdd(&hist[b], __popc(mask));
}

__global__ void __launch_bounds__(512)
cand_kernel(const __nv_bfloat16* __restrict__ approx) {
    extern __shared__ uint16_t keys16[];    // NFEAT uint16 (64 KB)
    __shared__ int hist[256];
    __shared__ int sb[2];
    __shared__ int cnt;
    __shared__ int eqbuf[CAND];
    __shared__ int eqn;

    int t = blockIdx.x, tid = threadIdx.x;
    const uint32_t* row = (const uint32_t*)(approx + (size_t)t * NFEAT);
    for (int i = tid; i < NFEAT / 2; i += 512) {
        uint32_t v = row[i];
        uint16_t a = (uint16_t)v, b = (uint16_t)(v >> 16);
        keys16[2 * i]     = (a & 0x8000) ? (uint16_t)~a : (uint16_t)(a | 0x8000);
        keys16[2 * i + 1] = (b & 0x8000) ? (uint16_t)~b : (uint16_t)(b | 0x8000);
    }
    __syncthreads();

    if (tid < 256) hist[tid] = 0;
    __syncthreads();
    for (int i = tid; i < NFEAT; i += 512)
        hist_add(hist, keys16[i] >> 8);
    __syncthreads();
    if (tid == 0) {
        int cum = 0, b = 255;
        for (; b >= 0; b--) { cum += hist[b]; if (cum >= CAND) break; }
        sb[0] = b;
        sb[1] = CAND - (cum - hist[b]);
    }
    __syncthreads();
    int hb = sb[0];
    int rem = sb[1];
    __syncthreads();

    if (tid < 256) hist[tid] = 0;
    __syncthreads();
    for (int i = tid; i < NFEAT; i += 512) {
        uint16_t u = keys16[i];
        if ((int)(u >> 8) == hb) hist_add(hist, u & 255);
    }
    __syncthreads();
    if (tid == 0) {
        int cum = 0, b = 255;
        for (; b >= 0; b--) { cum += hist[b]; if (cum >= rem) break; }
        sb[0] = b;
        sb[1] = rem - (cum - hist[b]);
    }
    __syncthreads();
    uint16_t thr = (uint16_t)((hb << 8) | sb[0]);
    rem = sb[1];

    if (tid == 0) { cnt = 0; eqn = 0; }
    __syncthreads();
    for (int i = tid; i < NFEAT; i += 512) {
        uint16_t u = keys16[i];
        if (u > thr) {
            int s = atomicAdd(&cnt, 1);
            g_selIdx[(size_t)t * MAXK + s] = i;
        } else if (u == thr) {
            int s = atomicAdd(&eqn, 1);
            if (s < CAND) eqbuf[s] = i;
        }
    }
    __syncthreads();
    if (tid == 0) {
        int n = eqn < CAND ? eqn : CAND;
        int base = cnt;
        for (int r2 = 0; r2 < rem; r2++) {
            int best = 0x7fffffff, bi = -1;
            for (int q = 0; q < n; q++)
                if (eqbuf[q] < best) { best = eqbuf[q]; bi = q; }
            if (bi < 0) break;
            eqbuf[bi] = 0x7fffffff;
            g_selIdx[(size_t)t * MAXK + base + r2] = best;
        }
    }
}

// ---------------------------------------------------------------------------
// 6) exact recompute of candidates, BIT-IDENTICAL to R3 GEMM accumulation
// ---------------------------------------------------------------------------
__global__ void __launch_bounds__(512)
recompute_kernel(const float* __restrict__ encw, const float* __restrict__ encb) {
    __shared__ float xs[DIN];
    __shared__ float bs[16][256];
    int t = blockIdx.x, tid = threadIdx.x;
    int lane = tid & 31, w = tid >> 5;

    const float4* xr = (const float4*)(g_xc + (size_t)t * DIN);
    for (int i = tid; i < DIN / 4; i += 512) ((float4*)xs)[i] = xr[i];
    __syncthreads();

    #pragma unroll 1
    for (int g = 0; g < CAND / 16; g++) {
        int c = w + 16 * g;
        int j = g_selIdx[(size_t)t * MAXK + c];
        const float* wr = encw + (size_t)j * DIN;

        #pragma unroll 1
        for (int bb = 0; bb < 8; bb++) {
            int b = lane + 32 * bb;
            int k0 = b * 16;
            float pb = 0.f;
            #pragma unroll
            for (int u = 0; u < 4; u++) {
                float4 wv = *(const float4*)(wr + k0 + u * 4);
                float4 xv = *(const float4*)(xs + k0 + u * 4);
                pb = fmaf(xv.x, wv.x, pb);
                pb = fmaf(xv.y, wv.y, pb);
                pb = fmaf(xv.z, wv.z, pb);
                pb = fmaf(xv.w, wv.w, pb);
            }
            bs[w][b] = pb;
        }
        __syncwarp();
        if (lane == 0) {
            float s = 0.f, cc = 0.f;
            #pragma unroll 8
            for (int b = 0; b < 256; b++) {
                float y  = bs[w][b] - cc;
                float tt = s + y;
                cc = (tt - s) - y;
                s = tt;
            }
            g_selVal[(size_t)t * MAXK + c] = (s + cc) + encb[j];
        }
        __syncwarp();
    }
}

// ---------------------------------------------------------------------------
// 7) zero features region
// ---------------------------------------------------------------------------
__global__ void zero_kernel(float4* __restrict__ p, size_t n4) {
    for (size_t i = (size_t)blockIdx.x * blockDim.x + threadIdx.x; i < n4;
         i += (size_t)gridDim.x * blockDim.x)
        p[i] = make_float4(0.f, 0.f, 0.f, 0.f);
}

// ---------------------------------------------------------------------------
// 8) final select among candidates (exact rank, ties by index) + scatter
// ---------------------------------------------------------------------------
__global__ void __launch_bounds__(CAND)
select_kernel(float* __restrict__ feats, const int* __restrict__ kp) {
    __shared__ float sv[CAND];
    __shared__ int   sj[CAND];
    __shared__ int   cnt;
    int t = blockIdx.x, c = threadIdx.x;
    int kk = kp ? *kp : 64;
    if (kk < 1) kk = 1;
    if (kk > CAND) kk = CAND;

    float v = g_selVal[(size_t)t * MAXK + c];
    int   j = g_selIdx[(size_t)t * MAXK + c];
    sv[c] = v; sj[c] = j;
    if (c == 0) cnt = 0;
    __syncthreads();

    int rank = 0;
    #pragma unroll 8
    for (int o = 0; o < CAND; o++)
        rank += (sv[o] > v) || (sv[o] == v && sj[o] < j);

    if (rank < kk) {
        int s = atomicAdd(&cnt, 1);
        float rv = fmaxf(v, 0.f);
        g_dIdx[(size_t)t * MAXK + s] = j;
        g_dVal[(size_t)t * MAXK + s] = rv;
        feats[(size_t)t * NFEAT + j] = rv;
    }
}

// ---------------------------------------------------------------------------
// 9) sparse decode + fused loss partial
// ---------------------------------------------------------------------------
__global__ void __launch_bounds__(512)
decode_kernel(float* __restrict__ pred, const float* __restrict__ y,
              const int* __restrict__ kp) {
    int t = blockIdx.x, tid = threadIdx.x;
    int kk = kp ? *kp : 64;
    if (kk < 1) kk = 1;
    if (kk > CAND) kk = CAND;

    float4 a0 = make_float4(0.f, 0.f, 0.f, 0.f), a1 = a0;
    const int*   si = g_dIdx + (size_t)t * MAXK;
    const float* sv = g_dVal + (size_t)t * MAXK;

    for (int s = 0; s < kk; s++) {
        int   j = si[s];
        float v = sv[s];
        const float4* r = (const float4*)(g_wT + (size_t)j * DOUTD);
        float4 w0 = r[tid], w1 = r[tid + 512];
        a0.x += v * w0.x; a0.y += v * w0.y; a0.z += v * w0.z; a0.w += v * w0.w;
        a1.x += v * w1.x; a1.y += v * w1.y; a1.z += v * w1.z; a1.w += v * w1.w;
    }

    float4* pr = (float4*)(pred + (size_t)t * DOUTD);
    pr[tid] = a0;
    pr[tid + 512] = a1;

    const float4* yr = (const float4*)(y + (size_t)t * DOUTD);
    float4 y0 = yr[tid], y1 = yr[tid + 512];
    float s2 = 0.f, d;
    d = a0.x - y0.x; s2 += d * d;  d = a0.y - y0.y; s2 += d * d;
    d = a0.z - y0.z; s2 += d * d;  d = a0.w - y0.w; s2 += d * d;
    d = a1.x - y1.x; s2 += d * d;  d = a1.y - y1.y; s2 += d * d;
    d = a1.z - y1.z; s2 += d * d;  d = a1.w - y1.w; s2 += d * d;

    #pragma unroll
    for (int o = 16; o; o >>= 1) s2 += __shfl_down_sync(0xffffffffu, s2, o);
    __shared__ float ws[16];
    int lane = tid & 31, wid = tid >> 5;
    if (lane == 0) ws[wid] = s2;
    __syncthreads();
    if (wid == 0) {
        float v2 = (lane < 16) ? ws[lane] : 0.f;
        #pragma unroll
        for (int o = 8; o; o >>= 1) v2 += __shfl_down_sync(0xffffffffu, v2, o);
        if (lane == 0) g_partial[t] = (double)v2;
    }
}

// ---------------------------------------------------------------------------
// 10) deterministic loss reduction
// ---------------------------------------------------------------------------
__global__ void finalize_kernel(float* __restrict__ scal) {
    __shared__ double sh[256];
    int tid = threadIdx.x;
    double s = 0.0;
    for (int i = tid; i < T_TOK; i += 256) s += g_partial[i];
    sh[tid] = s;
    __syncthreads();
    for (int o = 128; o; o >>= 1) {
        if (tid < o) sh[tid] += sh[tid + o];
        __syncthreads();
    }
    if (tid == 0) {
        float L = (float)(sh[0] / ((double)T_TOK * (double)DOUTD));
        scal[0] = L;
        scal[1] = L;
        scal[2] = 0.0f;
    }
}

// ---------------------------------------------------------------------------
extern "C" void kernel_launch(void* const* d_in, const int* in_sizes, int n_in,
                              void* d_out, int out_size) {
    const float* x    = (const float*)d_in[0];
    const float* y    = (const float*)d_in[1];
    const float* encw = (const float*)d_in[2];
    const float* encb = (const float*)d_in[3];
    const float* decw = (const float*)d_in[4];
    const float* bias = (const float*)d_in[5];
    const int*   kp   = (n_in > 6) ? (const int*)d_in[6] : nullptr;
    (void)in_sizes;

    size_t featN = (size_t)T_TOK * NFEAT;
    size_t predN = (size_t)T_TOK * DOUTD;
    float* out = (float*)d_out;
    size_t osz = (size_t)out_size;

    float *fb_pre = nullptr, *fb_pred = nullptr;
    cudaGetSymbolAddress((void**)&fb_pre,  g_preFB);
    cudaGetSymbolAddress((void**)&fb_pred, g_predFB);

    float* feats;
    float* pred;
    float* scal = nullptr;
    if (osz >= featN + predN) {
        feats = out;
        pred  = out + featN;
        if (osz >= featN + predN + 3) scal = out + featN + predN;
    } else if (osz >= featN) {
        feats = out;
        pred  = fb_pred;
    } else if (osz >= predN) {
        feats = fb_pre;
        pred  = out;
        if (osz >= predN + 3) scal = out + predN;
    } else {
        feats = fb_pre;
        pred  = fb_pred;
    }

    __nv_bfloat16* approxh = nullptr;
    cudaGetSymbolAddress((void**)&approxh, g_approxh);

    center_kernel<<<2048, 256>>>((const float4*)x, (const float4*)bias);
    convertw_kernel<<<4096, 256>>>((const float4*)encw);
    transpose_kernel<<<dim3(NFEAT / 64, DOUTD / 64), 256>>>(decw);

    cudaFuncSetAttribute(hgemm_kernel,
                         cudaFuncAttributeMaxDynamicSharedMemorySize, HG_SMEM);
    hgemm_kernel<<<dim3(T_TOK / 128, NFEAT / 64), 256, HG_SMEM>>>(encb, approxh);

    cudaFuncSetAttribute(cand_kernel,
                         cudaFuncAttributeMaxDynamicSharedMemorySize, NFEAT * 2);
    cand_kernel<<<T_TOK, 512, NFEAT * 2>>>(approxh);

    recompute_kernel<<<T_TOK, 512>>>(encw, encb);
    zero_kernel<<<8192, 256>>>((float4*)feats, featN / 4);
    select_kernel<<<T_TOK, CAND>>>(feats, kp);
    decode_kernel<<<T_TOK, 512>>>(pred, y, kp);
    if (scal) finalize_kernel<<<1, 256>>>(scal);
}

// round 15
// speedup vs baseline: 1.1370x; 1.1370x over previous
#include <cuda_runtime.h>
#include <cuda_bf16.h>
#include <cstdint>

// ---------------------------------------------------------------------------
// Transcoder: pre = (x - bias) @ enc_w^T + enc_b ; top-k ; sparse decode ; MSE
// Round 13: hgemm = R11 optimum (128x128, 64x32 warp tile, 2 CTAs/SM) with
// BK=64 (half the barriers). Final select fused into recompute epilogue.
// ---------------------------------------------------------------------------

#define T_TOK 4096
#define DIN   4096
#define NFEAT 32768
#define DOUTD 4096
#define MAXK  128
#define CAND  96

__device__ float          g_xc[(size_t)T_TOK * DIN];        // centered fp32
__device__ __nv_bfloat16  g_xb[(size_t)T_TOK * DIN];        // centered bf16
__device__ __nv_bfloat16  g_wb[(size_t)NFEAT * DIN];        // enc_w bf16
__device__ __nv_bfloat16  g_approxh[(size_t)T_TOK * NFEAT]; // approx pre (bf16)
__device__ float          g_wT[(size_t)NFEAT * DOUTD];      // dec_w transposed
__device__ int            g_selIdx[(size_t)T_TOK * MAXK];
__device__ int            g_dIdx[(size_t)T_TOK * MAXK];
__device__ float          g_dVal[(size_t)T_TOK * MAXK];
__device__ double         g_partial[T_TOK];
__device__ float          g_preFB[(size_t)T_TOK * NFEAT];
__device__ float          g_predFB[(size_t)T_TOK * DOUTD];

#define CPASYNC16(dst, src) \
    asm volatile("cp.async.cg.shared.global [%0], [%1], 16;" \
                 :: "r"(dst), "l"(src) : "memory")

// ---------------------------------------------------------------------------
// 1) center: fp32 + bf16 copies
// ---------------------------------------------------------------------------
__global__ void center_kernel(const float4* __restrict__ x,
                              const float4* __restrict__ bias) {
    size_t n = (size_t)T_TOK * DIN / 4;
    for (size_t i = (size_t)blockIdx.x * blockDim.x + threadIdx.x; i < n;
         i += (size_t)gridDim.x * blockDim.x) {
        float4 a = x[i];
        float4 b = bias[i & (DIN / 4 - 1)];
        float4 r;
        r.x = a.x - b.x; r.y = a.y - b.y; r.z = a.z - b.z; r.w = a.w - b.w;
        ((float4*)g_xc)[i] = r;
        __nv_bfloat162 h0 = __floats2bfloat162_rn(r.x, r.y);
        __nv_bfloat162 h1 = __floats2bfloat162_rn(r.z, r.w);
        uint2 pk;
        pk.x = *(uint32_t*)&h0;
        pk.y = *(uint32_t*)&h1;
        ((uint2*)g_xb)[i] = pk;
    }
}

// ---------------------------------------------------------------------------
// 2) enc_w -> bf16
// ---------------------------------------------------------------------------
__global__ void convertw_kernel(const float4* __restrict__ W) {
    size_t n = (size_t)NFEAT * DIN / 4;
    for (size_t i = (size_t)blockIdx.x * blockDim.x + threadIdx.x; i < n;
         i += (size_t)gridDim.x * blockDim.x) {
        float4 a = W[i];
        __nv_bfloat162 h0 = __floats2bfloat162_rn(a.x, a.y);
        __nv_bfloat162 h1 = __floats2bfloat162_rn(a.z, a.w);
        uint2 pk;
        pk.x = *(uint32_t*)&h0;
        pk.y = *(uint32_t*)&h1;
        ((uint2*)g_wb)[i] = pk;
    }
}

// ---------------------------------------------------------------------------
// 3) transpose dec_w -> g_wT [NFEAT, DOUTD]; 64x64 tile, float4 both ways
// ---------------------------------------------------------------------------
__global__ void __launch_bounds__(256)
transpose_kernel(const float* __restrict__ W) {
    __shared__ float t[64][65];
    int j0 = blockIdx.x * 64;
    int d0 = blockIdx.y * 64;
    int tx = threadIdx.x & 15;
    int ty = threadIdx.x >> 4;
    #pragma unroll
    for (int i = 0; i < 4; i++) {
        int d = ty + i * 16;
        float4 v = *(const float4*)(W + (size_t)(d0 + d) * NFEAT + j0 + tx * 4);
        t[d][tx * 4 + 0] = v.x;
        t[d][tx * 4 + 1] = v.y;
        t[d][tx * 4 + 2] = v.z;
        t[d][tx * 4 + 3] = v.w;
    }
    __syncthreads();
    #pragma unroll
    for (int i = 0; i < 4; i++) {
        int j = ty + i * 16;
        float4 v;
        v.x = t[tx * 4 + 0][j];
        v.y = t[tx * 4 + 1][j];
        v.z = t[tx * 4 + 2][j];
        v.w = t[tx * 4 + 3][j];
        *(float4*)(g_wT + (size_t)(j0 + j) * DOUTD + d0 + tx * 4) = v;
    }
}

// ---------------------------------------------------------------------------
// 4) HMMA approx GEMM: approx[t,f] = bf16(xb[t,:].wb[f,:] + encb[f])
//    CTA 128x128, BK=64, 8 warps (2m x 4n), warp tile 64x32, 2-stage
//    cp.async, 2 CTAs/SM (launch_bounds(256,2); 72KB smem/CTA).
// ---------------------------------------------------------------------------
#define RSTR   144                     // bytes per smem row (64 bf16 + pad)
#define A_SZ   (128 * RSTR)            // 18432 B
#define B_SZ   (128 * RSTR)            // 18432 B
#define STG_SZ (A_SZ + B_SZ)           // 36864 B
#define HG_SMEM (2 * STG_SZ)           // 73728 B
#define NCH    (DIN / 64)              // 64 chunks

__global__ void __launch_bounds__(256, 2)
hgemm_kernel(const float* __restrict__ encb, __nv_bfloat16* __restrict__ C) {
    extern __shared__ char smem[];
    uint32_t sbase;
    asm("{ .reg .u64 t; cvta.to.shared.u64 t, %1; cvt.u32.u64 %0, t; }"
        : "=r"(sbase) : "l"(smem));

    int tid  = threadIdx.x;
    int lane = tid & 31;
    int warp = tid >> 5;
    int wm   = warp & 1;          // 0..1  (64-row half)
    int wn   = warp >> 1;         // 0..3  (32-col slice)

    int mBase = blockIdx.x * 128;
    int nBase = blockIdx.y * 128;

    const __nv_bfloat16* gA0 = g_xb + (size_t)mBase * DIN;
    const __nv_bfloat16* gB0 = g_wb + (size_t)nBase * DIN;

    float acc[4][4][4];
    #pragma unroll
    for (int mi = 0; mi < 4; mi++)
        #pragma unroll
        for (int nj = 0; nj < 4; nj++)
            #pragma unroll
            for (int r = 0; r < 4; r++) acc[mi][nj][r] = 0.f;

    int lr = tid >> 3, lq = tid & 7;   // lr 0..31, lq 0..7 (16B chunk in 128B)
    auto load_stage = [&](int kb, int s) {
        uint32_t aB = sbase + s * STG_SZ;
        uint32_t bB = aB + A_SZ;
        #pragma unroll
        for (int i = 0; i < 4; i++) {             // A: 128 rows
            int r = lr + i * 32;
            const __nv_bfloat16* src = gA0 + (size_t)r * DIN + kb + lq * 8;
            CPASYNC16(aB + r * RSTR + lq * 16, src);
        }
        #pragma unroll
        for (int i = 0; i < 4; i++) {             // B: 128 rows
            int r = lr + i * 32;
            const __nv_bfloat16* src = gB0 + (size_t)r * DIN + kb + lq * 8;
            CPASYNC16(bB + r * RSTR + lq * 16, src);
        }
        asm volatile("cp.async.commit_group;" ::: "memory");
    };

    load_stage(0, 0);
    asm volatile("cp.async.wait_group 0;" ::: "memory");
    __syncthreads();

    // per-lane ldmatrix components
    int aRow = (lane & 15);
    int aKB  = (lane >> 4) * 16;            // bytes
    int bRow = ((lane >> 4) << 3) + (lane & 7);
    int bKB  = ((lane >> 3) & 1) * 16;      // bytes

    for (int c = 0; c < NCH; c++) {
        int s = c & 1;
        bool has = (c + 1) < NCH;
        if (has) load_stage((c + 1) * 64, s ^ 1);

        uint32_t aB = sbase + s * STG_SZ;
        uint32_t bB = aB + A_SZ;

        #pragma unroll
        for (int ks = 0; ks < 4; ks++) {          // four k16 slices
            uint32_t af[4][4];
            #pragma unroll
            for (int mi = 0; mi < 4; mi++) {
                int row = wm * 64 + mi * 16 + aRow;
                uint32_t sa = aB + row * RSTR + ks * 32 + aKB;
                asm volatile(
                    "ldmatrix.sync.aligned.m8n8.x4.shared.b16 {%0,%1,%2,%3}, [%4];"
                    : "=r"(af[mi][0]), "=r"(af[mi][1]),
                      "=r"(af[mi][2]), "=r"(af[mi][3]) : "r"(sa));
            }
            uint32_t bf[2][4];
            #pragma unroll
            for (int p = 0; p < 2; p++) {
                int row = wn * 32 + p * 16 + bRow;
                uint32_t sb = bB + row * RSTR + ks * 32 + bKB;
                asm volatile(
                    "ldmatrix.sync.aligned.m8n8.x4.shared.b16 {%0,%1,%2,%3}, [%4];"
                    : "=r"(bf[p][0]), "=r"(bf[p][1]),
                      "=r"(bf[p][2]), "=r"(bf[p][3]) : "r"(sb));
            }
            #pragma unroll
            for (int mi = 0; mi < 4; mi++)
                #pragma unroll
                for (int nj = 0; nj < 4; nj++) {
                    uint32_t b0 = bf[nj >> 1][(nj & 1) * 2 + 0];
                    uint32_t b1 = bf[nj >> 1][(nj & 1) * 2 + 1];
                    asm volatile(
                        "mma.sync.aligned.m16n8k16.row.col.f32.bf16.bf16.f32 "
                        "{%0,%1,%2,%3}, {%4,%5,%6,%7}, {%8,%9}, {%0,%1,%2,%3};"
                        : "+f"(acc[mi][nj][0]), "+f"(acc[mi][nj][1]),
                          "+f"(acc[mi][nj][2]), "+f"(acc[mi][nj][3])
                        : "r"(af[mi][0]), "r"(af[mi][1]),
                          "r"(af[mi][2]), "r"(af[mi][3]),
                          "r"(b0), "r"(b1));
                }
        }

        if (has) asm volatile("cp.async.wait_group 0;" ::: "memory");
        __syncthreads();
    }

    // epilogue: add enc_b, convert to bf16, store
    #pragma unroll
    for (int mi = 0; mi < 4; mi++) {
        int m0 = mBase + wm * 64 + mi * 16 + (lane >> 2);
        #pragma unroll
        for (int nj = 0; nj < 4; nj++) {
            int col = nBase + wn * 32 + nj * 8 + (lane & 3) * 2;
            float2 e = *(const float2*)(encb + col);
            __nv_bfloat162 h0 = __floats2bfloat162_rn(acc[mi][nj][0] + e.x,
                                                      acc[mi][nj][1] + e.y);
            __nv_bfloat162 h1 = __floats2bfloat162_rn(acc[mi][nj][2] + e.x,
                                                      acc[mi][nj][3] + e.y);
            *(uint32_t*)(C + (size_t)m0 * NFEAT + col)       = *(uint32_t*)&h0;
            *(uint32_t*)(C + (size_t)(m0 + 8) * NFEAT + col) = *(uint32_t*)&h1;
        }
    }
}

// ---------------------------------------------------------------------------
// 5) candidate select: 2-pass radix top-CAND, warp-aggregated histograms
// ---------------------------------------------------------------------------
__device__ __forceinline__ void hist_add(int* hist, int b) {
    unsigned mask = __match_any_sync(__activemask(), b);
    int leader = __ffs(mask) - 1;
    if ((int)(threadIdx.x & 31) == leader)
        atomicAdd(&hist[b], __popc(mask));
}

__global__ void __launch_bounds__(512)
cand_kernel(const __nv_bfloat16* __restrict__ approx) {
    extern __shared__ uint16_t keys16[];    // NFEAT uint16 (64 KB)
    __shared__ int hist[256];
    __shared__ int sb[2];
    __shared__ int cnt;
    __shared__ int eqbuf[CAND];
    __shared__ int eqn;

    int t = blockIdx.x, tid = threadIdx.x;
    const uint32_t* row = (const uint32_t*)(approx + (size_t)t * NFEAT);
    for (int i = tid; i < NFEAT / 2; i += 512) {
        uint32_t v = row[i];
        uint16_t a = (uint16_t)v, b = (uint16_t)(v >> 16);
        keys16[2 * i]     = (a & 0x8000) ? (uint16_t)~a : (uint16_t)(a | 0x8000);
        keys16[2 * i + 1] = (b & 0x8000) ? (uint16_t)~b : (uint16_t)(b | 0x8000);
    }
    __syncthreads();

    if (tid < 256) hist[tid] = 0;
    __syncthreads();
    for (int i = tid; i < NFEAT; i += 512)
        hist_add(hist, keys16[i] >> 8);
    __syncthreads();
    if (tid == 0) {
        int cum = 0, b = 255;
        for (; b >= 0; b--) { cum += hist[b]; if (cum >= CAND) break; }
        sb[0] = b;
        sb[1] = CAND - (cum - hist[b]);
    }
    __syncthreads();
    int hb = sb[0];
    int rem = sb[1];
    __syncthreads();

    if (tid < 256) hist[tid] = 0;
    __syncthreads();
    for (int i = tid; i < NFEAT; i += 512) {
        uint16_t u = keys16[i];
        if ((int)(u >> 8) == hb) hist_add(hist, u & 255);
    }
    __syncthreads();
    if (tid == 0) {
        int cum = 0, b = 255;
        for (; b >= 0; b--) { cum += hist[b]; if (cum >= rem) break; }
        sb[0] = b;
        sb[1] = rem - (cum - hist[b]);
    }
    __syncthreads();
    uint16_t thr = (uint16_t)((hb << 8) | sb[0]);
    rem = sb[1];

    if (tid == 0) { cnt = 0; eqn = 0; }
    __syncthreads();
    for (int i = tid; i < NFEAT; i += 512) {
        uint16_t u = keys16[i];
        if (u > thr) {
            int s = atomicAdd(&cnt, 1);
            g_selIdx[(size_t)t * MAXK + s] = i;
        } else if (u == thr) {
            int s = atomicAdd(&eqn, 1);
            if (s < CAND) eqbuf[s] = i;
        }
    }
    __syncthreads();
    if (tid == 0) {
        int n = eqn < CAND ? eqn : CAND;
        int base = cnt;
        for (int r2 = 0; r2 < rem; r2++) {
            int best = 0x7fffffff, bi = -1;
            for (int q = 0; q < n; q++)
                if (eqbuf[q] < best) { best = eqbuf[q]; bi = q; }
            if (bi < 0) break;
            eqbuf[bi] = 0x7fffffff;
            g_selIdx[(size_t)t * MAXK + base + r2] = best;
        }
    }
}

// ---------------------------------------------------------------------------
// 6) exact recompute (bit-identical to R3) + FUSED final select/scatter
// ---------------------------------------------------------------------------
__global__ void __launch_bounds__(512)
recompute_kernel(const float* __restrict__ encw, const float* __restrict__ encb,
                 float* __restrict__ feats, const int* __restrict__ kp) {
    __shared__ float xs[DIN];
    __shared__ float bs[16][256];
    __shared__ float cv[CAND];
    __shared__ int   cj[CAND];
    __shared__ int   cnt2;
    int t = blockIdx.x, tid = threadIdx.x;
    int lane = tid & 31, w = tid >> 5;

    const float4* xr = (const float4*)(g_xc + (size_t)t * DIN);
    for (int i = tid; i < DIN / 4; i += 512) ((float4*)xs)[i] = xr[i];
    if (tid == 0) cnt2 = 0;
    __syncthreads();

    #pragma unroll 1
    for (int g = 0; g < CAND / 16; g++) {
        int c = w + 16 * g;
        int j = g_selIdx[(size_t)t * MAXK + c];
        const float* wr = encw + (size_t)j * DIN;

        #pragma unroll 1
        for (int bb = 0; bb < 8; bb++) {
            int b = lane + 32 * bb;
            int k0 = b * 16;
            float pb = 0.f;
            #pragma unroll
            for (int u = 0; u < 4; u++) {
                float4 wv = *(const float4*)(wr + k0 + u * 4);
                float4 xv = *(const float4*)(xs + k0 + u * 4);
                pb = fmaf(xv.x, wv.x, pb);
                pb = fmaf(xv.y, wv.y, pb);
                pb = fmaf(xv.z, wv.z, pb);
                pb = fmaf(xv.w, wv.w, pb);
            }
            bs[w][b] = pb;
        }
        __syncwarp();
        if (lane == 0) {
            float s = 0.f, cc = 0.f;
            #pragma unroll 8
            for (int b = 0; b < 256; b++) {
                float y  = bs[w][b] - cc;
                float tt = s + y;
                cc = (tt - s) - y;
                s = tt;
            }
            cv[c] = (s + cc) + encb[j];
            cj[c] = j;
        }
        __syncwarp();
    }
    __syncthreads();

    // fused final select: exact rank among CAND, ties by index, scatter
    if (tid < CAND) {
        int kk = kp ? *kp : 64;
        if (kk < 1) kk = 1;
        if (kk > CAND) kk = CAND;
        float v = cv[tid];
        int   j = cj[tid];
        int rank = 0;
        #pragma unroll 8
        for (int o = 0; o < CAND; o++)
            rank += (cv[o] > v) || (cv[o] == v && cj[o] < j);
        if (rank < kk) {
            int s = atomicAdd(&cnt2, 1);
            float rv = fmaxf(v, 0.f);
            g_dIdx[(size_t)t * MAXK + s] = j;
            g_dVal[(size_t)t * MAXK + s] = rv;
            feats[(size_t)t * NFEAT + j] = rv;
        }
    }
}

// ---------------------------------------------------------------------------
// 7) zero features region
// ---------------------------------------------------------------------------
__global__ void zero_kernel(float4* __restrict__ p, size_t n4) {
    for (size_t i = (size_t)blockIdx.x * blockDim.x + threadIdx.x; i < n4;
         i += (size_t)gridDim.x * blockDim.x)
        p[i] = make_float4(0.f, 0.f, 0.f, 0.f);
}

// ---------------------------------------------------------------------------
// 9) sparse decode + fused loss partial
// ---------------------------------------------------------------------------
__global__ void __launch_bounds__(512)
decode_kernel(float* __restrict__ pred, const float* __restrict__ y,
              const int* __restrict__ kp) {
    int t = blockIdx.x, tid = threadIdx.x;
    int kk = kp ? *kp : 64;
    if (kk < 1) kk = 1;
    if (kk > CAND) kk = CAND;

    float4 a0 = make_float4(0.f, 0.f, 0.f, 0.f), a1 = a0;
    const int*   si = g_dIdx + (size_t)t * MAXK;
    const float* sv = g_dVal + (size_t)t * MAXK;

    for (int s = 0; s < kk; s++) {
        int   j = si[s];
        float v = sv[s];
        const float4* r = (const float4*)(g_wT + (size_t)j * DOUTD);
        float4 w0 = r[tid], w1 = r[tid + 512];
        a0.x += v * w0.x; a0.y += v * w0.y; a0.z += v * w0.z; a0.w += v * w0.w;
        a1.x += v * w1.x; a1.y += v * w1.y; a1.z += v * w1.z; a1.w += v * w1.w;
    }

    float4* pr = (float4*)(pred + (size_t)t * DOUTD);
    pr[tid] = a0;
    pr[tid + 512] = a1;

    const float4* yr = (const float4*)(y + (size_t)t * DOUTD);
    float4 y0 = yr[tid], y1 = yr[tid + 512];
    float s2 = 0.f, d;
    d = a0.x - y0.x; s2 += d * d;  d = a0.y - y0.y; s2 += d * d;
    d = a0.z - y0.z; s2 += d * d;  d = a0.w - y0.w; s2 += d * d;
    d = a1.x - y1.x; s2 += d * d;  d = a1.y - y1.y; s2 += d * d;
    d = a1.z - y1.z; s2 += d * d;  d = a1.w - y1.w; s2 += d * d;

    #pragma unroll
    for (int o = 16; o; o >>= 1) s2 += __shfl_down_sync(0xffffffffu, s2, o);
    __shared__ float ws[16];
    int lane = tid & 31, wid = tid >> 5;
    if (lane == 0) ws[wid] = s2;
    __syncthreads();
    if (wid == 0) {
        float v2 = (lane < 16) ? ws[lane] : 0.f;
        #pragma unroll
        for (int o = 8; o; o >>= 1) v2 += __shfl_down_sync(0xffffffffu, v2, o);
        if (lane == 0) g_partial[t] = (double)v2;
    }
}

// ---------------------------------------------------------------------------
// 10) deterministic loss reduction
// ---------------------------------------------------------------------------
__global__ void finalize_kernel(float* __restrict__ scal) {
    __shared__ double sh[256];
    int tid = threadIdx.x;
    double s = 0.0;
    for (int i = tid; i < T_TOK; i += 256) s += g_partial[i];
    sh[tid] = s;
    __syncthreads();
    for (int o = 128; o; o >>= 1) {
        if (tid < o) sh[tid] += sh[tid + o];
        __syncthreads();
    }
    if (tid == 0) {
        float L = (float)(sh[0] / ((double)T_TOK * (double)DOUTD));
        scal[0] = L;
        scal[1] = L;
        scal[2] = 0.0f;
    }
}

// ---------------------------------------------------------------------------
extern "C" void kernel_launch(void* const* d_in, const int* in_sizes, int n_in,
                              void* d_out, int out_size) {
    const float* x    = (const float*)d_in[0];
    const float* y    = (const float*)d_in[1];
    const float* encw = (const float*)d_in[2];
    const float* encb = (const float*)d_in[3];
    const float* decw = (const float*)d_in[4];
    const float* bias = (const float*)d_in[5];
    const int*   kp   = (n_in > 6) ? (const int*)d_in[6] : nullptr;
    (void)in_sizes;

    size_t featN = (size_t)T_TOK * NFEAT;
    size_t predN = (size_t)T_TOK * DOUTD;
    float* out = (float*)d_out;
    size_t osz = (size_t)out_size;

    float *fb_pre = nullptr, *fb_pred = nullptr;
    cudaGetSymbolAddress((void**)&fb_pre,  g_preFB);
    cudaGetSymbolAddress((void**)&fb_pred, g_predFB);

    float* feats;
    float* pred;
    float* scal = nullptr;
    if (osz >= featN + predN) {
        feats = out;
        pred  = out + featN;
        if (osz >= featN + predN + 3) scal = out + featN + predN;
    } else if (osz >= featN) {
        feats = out;
        pred  = fb_pred;
    } else if (osz >= predN) {
        feats = fb_pre;
        pred  = out;
        if (osz >= predN + 3) scal = out + predN;
    } else {
        feats = fb_pre;
        pred  = fb_pred;
    }

    __nv_bfloat16* approxh = nullptr;
    cudaGetSymbolAddress((void**)&approxh, g_approxh);

    center_kernel<<<2048, 256>>>((const float4*)x, (const float4*)bias);
    convertw_kernel<<<4096, 256>>>((const float4*)encw);
    transpose_kernel<<<dim3(NFEAT / 64, DOUTD / 64), 256>>>(decw);

    cudaFuncSetAttribute(hgemm_kernel,
                         cudaFuncAttributeMaxDynamicSharedMemorySize, HG_SMEM);
    hgemm_kernel<<<dim3(T_TOK / 128, NFEAT / 128), 256, HG_SMEM>>>(encb, approxh);

    cudaFuncSetAttribute(cand_kernel,
                         cudaFuncAttributeMaxDynamicSharedMemorySize, NFEAT * 2);
    cand_kernel<<<T_TOK, 512, NFEAT * 2>>>(approxh);

    zero_kernel<<<8192, 256>>>((float4*)feats, featN / 4);
    recompute_kernel<<<T_TOK, 512>>>(encw, encb, feats, kp);
    decode_kernel<<<T_TOK, 512>>>(pred, y, kp);
    if (scal) finalize_kernel<<<1, 256>>>(scal);
}